// round 10
// baseline (speedup 1.0000x reference)
#include <cuda_runtime.h>
#include <math.h>
#include <stdint.h>

#define BB 2
#define SS 4096
#define EE 1024
#define HH 16
#define DD 64
#define WIN_ 256
#define MM (BB*SS)   // 8192

#define XT_ELEMS ((size_t)MM*EE)     // 8388608
#define WT_ELEMS ((size_t)EE*EE)     // 1048576

// scratch (allocation-free: __device__ globals)
// tf32 bit patterns everywhere the tensor cores read
static __device__ uint32_t g_xt[XT_ELEMS];             // x, tf32
static __device__ uint32_t g_wt[4*WT_ELEMS];           // Wq,Wk,Wv,Wo, tf32
static __device__ uint32_t g_q[(size_t)BB*HH*SS*DD];   // [b][h][s][d], rope'd + scaled, tf32
static __device__ uint32_t g_k[(size_t)BB*HH*SS*DD];   // [b][h][s][d], rope'd, tf32
static __device__ uint32_t g_v[(size_t)BB*HH*SS*DD];   // [b][h][s][d], tf32
static __device__ uint32_t g_ctx[(size_t)MM*EE];       // [b][s][e], tf32

// rope over the HEAD axis: angle = head_idx * 10000^{-(j%32)/32}, interleaved rotation
__device__ __forceinline__ void rope_pair(float& v0, float& v1, int h, int j) {
    const float C = 0.28782313662425572f; // ln(10000)/32
    float invA = __expf(-(float)( j      & 31) * C);
    float invB = __expf(-(float)((j + 1) & 31) * C);
    float sa, ca, sb, cb;
    __sincosf((float)h * invA, &sa, &ca);
    __sincosf((float)h * invB, &sb, &cb);
    float r0 = v0 * ca - v1 * sa;
    float r1 = v1 * cb + v0 * sb;
    v0 = r0; v1 = r1;
}

__device__ __forceinline__ uint32_t f2tf(float f) {
    uint32_t u;
    asm("cvt.rna.tf32.f32 %0, %1;" : "=r"(u) : "f"(f));
    return u;
}

__device__ __forceinline__ void mma_tf32(float (&c)[4], const uint32_t (&a)[4], const uint32_t b0, const uint32_t b1) {
    asm volatile(
        "mma.sync.aligned.m16n8k8.row.col.f32.tf32.tf32.f32 "
        "{%0,%1,%2,%3},{%4,%5,%6,%7},{%8,%9},{%0,%1,%2,%3};"
        : "+f"(c[0]), "+f"(c[1]), "+f"(c[2]), "+f"(c[3])
        : "r"(a[0]), "r"(a[1]), "r"(a[2]), "r"(a[3]), "r"(b0), "r"(b1));
}
__device__ __forceinline__ void mma_tf32v(float (&c)[4], const uint32_t (&a)[4], const uint32_t (&b)[2]) {
    mma_tf32(c, a, b[0], b[1]);
}

// ldmatrix on 32-bit data: an 8x8-uint32 tile viewed as 8x16 b16 gives lane l
// word (l%4) of row (l/4) — exactly the tf32 mma fragment mapping.
__device__ __forceinline__ void ldsm_x4(uint32_t (&d)[4], uint32_t addr) {
    asm volatile("ldmatrix.sync.aligned.m8n8.x4.shared.b16 {%0,%1,%2,%3}, [%4];"
        : "=r"(d[0]), "=r"(d[1]), "=r"(d[2]), "=r"(d[3]) : "r"(addr));
}
__device__ __forceinline__ void ldsm_x2(uint32_t (&d)[2], uint32_t addr) {
    asm volatile("ldmatrix.sync.aligned.m8n8.x2.shared.b16 {%0,%1}, [%2];"
        : "=r"(d[0]), "=r"(d[1]) : "r"(addr));
}

__device__ __forceinline__ void cp16(uint32_t smem_addr, const void* gptr) {
    asm volatile("cp.async.cg.shared.global [%0], [%1], 16;" :: "r"(smem_addr), "l"(gptr));
}
#define CP_COMMIT() asm volatile("cp.async.commit_group;")
#define CP_WAIT2()  asm volatile("cp.async.wait_group 2;")

// ---------------- one-time tf32 conversion of x and W matrices ----------------
__global__ __launch_bounds__(256)
void conv_kernel(const float* __restrict__ x,
                 const float* __restrict__ wq, const float* __restrict__ wk,
                 const float* __restrict__ wv, const float* __restrict__ wo)
{
    size_t i4 = (size_t)blockIdx.x * 256 + threadIdx.x;
    const size_t x4 = XT_ELEMS / 4;
    const size_t w4 = WT_ELEMS / 4;
    if (i4 >= x4 + 4 * w4) return;
    const float* src; uint32_t* dst; size_t off;
    if (i4 < x4) { src = x; dst = g_xt; off = i4 * 4; }
    else {
        size_t j = i4 - x4;
        int w = (int)(j / w4);
        off = (j - (size_t)w * w4) * 4;
        src = (w == 0) ? wq : (w == 1) ? wk : (w == 2) ? wv : wo;
        dst = g_wt + (size_t)w * WT_ELEMS;
    }
    float4 v = *reinterpret_cast<const float4*>(src + off);
    *reinterpret_cast<uint4*>(dst + off) =
        make_uint4(f2tf(v.x), f2tf(v.y), f2tf(v.z), f2tf(v.w));
}

// ---------------- projection GEMM (TF32, cp.async 4-stage, 256x128 tile, 8 warps) ----------------
// 256 threads -> 255-reg cap -> room for explicit fragment double-buffering.
// MODE 0: A = g_xt, W = g_wt[z]; rope epilogue; writes g_q/g_k/g_v [b,h,s,d] tf32
// MODE 1: A = g_ctx, W = g_wt[3]; writes d_out [m,n] fp32
#define ASTRIDE 36
#define STAGE_ELEMS ((256 + 128) * ASTRIDE)          // 13824 uint32
#define STAGE_BYTES (STAGE_ELEMS * 4)                // 55296
#define NSTAGE 4
#define SMEM_PROJ   (NSTAGE * STAGE_BYTES)           // 221184

template<int MODE>
__global__ __launch_bounds__(256, 1)
void proj_mma(const float* __restrict__ b0, const float* __restrict__ b1,
              const float* __restrict__ b2, float* __restrict__ out)
{
    extern __shared__ uint32_t sm_u[];
    const uint32_t smem_b = (uint32_t)__cvta_generic_to_shared(sm_u);

    const int z = blockIdx.z;
    const uint32_t* A = (MODE == 1) ? g_ctx : g_xt;
    const uint32_t* W = g_wt + (size_t)((MODE == 1) ? 3 : z) * WT_ELEMS;
    const float* bias = (MODE == 1) ? b0 : (z == 0 ? b0 : (z == 1 ? b1 : b2));

    const int tid   = threadIdx.x;
    const int lane  = tid & 31;
    const int warp  = tid >> 5;            // 0..7
    const int warpM = warp >> 1;           // 0..3 -> 64-row slab
    const int warpN = warp & 1;            // 0..1 -> 64-col slab
    const int grp   = lane >> 2;           // 0..7
    const int qid   = lane & 3;            // 0..3
    const int mBase = blockIdx.y * 256;
    const int nBase = blockIdx.x * 128;

    const int ldRow = tid >> 3;            // 0..31
    const int ldCol = (tid & 7) * 4;       // 0..28

    // per-lane ldmatrix base offsets (bytes)
    const int sub = lane >> 3;             // 0..3
    const int rin = lane & 7;              // 0..7
    // A x4: tiles = {rows 0-7 / 8-15} x {word-cols 0-3 / 4-7}
    const uint32_t aFragOff = (uint32_t)((warpM * 64 + (sub & 1) * 8 + rin) * ASTRIDE + (sub >> 1) * 4) * 4;
    // B x4: tiles = {nf even / nf odd within a pair} x {word-cols 0-3 / 4-7}
    //   sub0:(nf0,h0) sub1:(nf0,h1) sub2:(nf1,h0) sub3:(nf1,h1)
    const uint32_t bFragOff = (uint32_t)((256 * ASTRIDE) + (warpN * 64 + (sub >> 1) * 8 + rin) * ASTRIDE + (sub & 1) * 4) * 4;

    // async stage loader: A 256x32, B 128x32 per slab
    auto issue = [&](int stage, int k0) {
        uint32_t base = smem_b + stage * STAGE_BYTES;
        int kofs = k0 * 32 + ldCol;
        #pragma unroll
        for (int p = 0; p < 8; p++) {
            int r = ldRow + p * 32;
            cp16(base + (uint32_t)(r * ASTRIDE + ldCol) * 4,
                 A + (size_t)(mBase + r) * EE + kofs);
        }
        #pragma unroll
        for (int p = 0; p < 4; p++) {
            int r = ldRow + p * 32;
            cp16(base + (uint32_t)((256 * ASTRIDE) + r * ASTRIDE + ldCol) * 4,
                 W + (size_t)(nBase + r) * EE + kofs);
        }
    };

    float acc[4][8][4];
    #pragma unroll
    for (int mf = 0; mf < 4; mf++)
        #pragma unroll
        for (int nf = 0; nf < 8; nf++)
            #pragma unroll
            for (int r = 0; r < 4; r++) acc[mf][nf][r] = 0.f;

    const int NIT = EE / 32;   // 32
    issue(0, 0); CP_COMMIT();
    issue(1, 1); CP_COMMIT();
    issue(2, 2); CP_COMMIT();

    uint32_t af[2][4][4];     // [buf][mf][4]
    uint32_t bf[2][4][4];     // [buf][nfPair][4] = {nf0.b0, nf0.b1, nf1.b0, nf1.b1}

    int stage = 0;
    for (int k0 = 0; k0 < NIT; k0++) {
        CP_WAIT2();
        __syncthreads();
        {   // prefetch slab k0+3 into the stage consumed at k0-1 (guarded by the sync above)
            if (k0 + 3 < NIT) {
                int ns = stage + 3; if (ns >= NSTAGE) ns -= NSTAGE;
                issue(ns, k0 + 3);
            }
            CP_COMMIT();
        }

        const uint32_t aBase = smem_b + stage * STAGE_BYTES + aFragOff;
        const uint32_t bBase = smem_b + stage * STAGE_BYTES + bFragOff;

        // ks-pipelined fragment loads: load ks+1 while issuing MMAs for ks
        #pragma unroll
        for (int mf = 0; mf < 4; mf++)
            ldsm_x4(af[0][mf], aBase + (uint32_t)(mf * 16 * ASTRIDE) * 4);
        #pragma unroll
        for (int pr = 0; pr < 4; pr++)
            ldsm_x4(bf[0][pr], bBase + (uint32_t)(pr * 16 * ASTRIDE) * 4);

        #pragma unroll
        for (int ks = 0; ks < 4; ks++) {
            const int cur = ks & 1, nxt = cur ^ 1;
            if (ks < 3) {
                #pragma unroll
                for (int mf = 0; mf < 4; mf++)
                    ldsm_x4(af[nxt][mf], aBase + (uint32_t)(mf * 16 * ASTRIDE + (ks + 1) * 8) * 4);
                #pragma unroll
                for (int pr = 0; pr < 4; pr++)
                    ldsm_x4(bf[nxt][pr], bBase + (uint32_t)(pr * 16 * ASTRIDE + (ks + 1) * 8) * 4);
            }
            #pragma unroll
            for (int mf = 0; mf < 4; mf++)
                #pragma unroll
                for (int pr = 0; pr < 4; pr++) {
                    mma_tf32(acc[mf][pr * 2 + 0], af[cur][mf], bf[cur][pr][0], bf[cur][pr][1]);
                    mma_tf32(acc[mf][pr * 2 + 1], af[cur][mf], bf[cur][pr][2], bf[cur][pr][3]);
                }
        }

        stage++; if (stage >= NSTAGE) stage = 0;
    }

    // epilogue: bias (+rope/scale for MODE 0), scatter
    #pragma unroll
    for (int mf = 0; mf < 4; mf++) {
        #pragma unroll
        for (int half = 0; half < 2; half++) {
            int row = mBase + warpM * 64 + mf * 16 + grp + half * 8;
            int bb   = row >> 12;
            int srow = row & 4095;
            #pragma unroll
            for (int nf = 0; nf < 8; nf++) {
                int col = nBase + warpN * 64 + nf * 8 + qid * 2;
                float v0 = acc[mf][nf][half * 2 + 0] + bias[col];
                float v1 = acc[mf][nf][half * 2 + 1] + bias[col + 1];
                if (MODE == 1) {
                    *reinterpret_cast<float2*>(&out[(size_t)row * EE + col]) = make_float2(v0, v1);
                } else {
                    int h = col >> 6;
                    int j = col & 63;     // even
                    if (z <= 1) rope_pair(v0, v1, h, j);
                    if (z == 0) { v0 *= 0.125f; v1 *= 0.125f; }
                    uint32_t* dst = (z == 0) ? g_q : (z == 1) ? g_k : g_v;
                    size_t idx = (((size_t)bb * HH + h) * SS + srow) * DD + j;
                    *reinterpret_cast<uint2*>(&dst[idx]) = make_uint2(f2tf(v0), f2tf(v1));
                }
            }
        }
    }
}

// ---------------- sliding-window attention (flash-style, TF32 tensor cores, ldmatrix) ----------------
// grid (qb=4, c=16, bh=32); block 128 (4 warps); each warp owns 16 query rows.
#define AST 68                                   // smem stride (uint32)
#define SMEM_ATTN (3 * 64 * AST * 4)             // Qs(->Ps) + Ks + Vs = 52224 B

__global__ __launch_bounds__(128)
void attn_mma_kernel()
{
    extern __shared__ uint32_t sm[];
    uint32_t* Qs = sm;                  // 64 x AST (reused as Ps after Q frags are in regs)
    uint32_t* Ks = sm + 64 * AST;
    uint32_t* Vs = sm + 2 * 64 * AST;
    float*    Ps = reinterpret_cast<float*>(Qs);
    const uint32_t smA = (uint32_t)__cvta_generic_to_shared(sm);

    const int qb = blockIdx.x;
    const int c  = blockIdx.y;
    const int bh = blockIdx.z;
    const int tid  = threadIdx.x;
    const int w    = tid >> 5;
    const int lane = tid & 31;
    const int grp  = lane >> 2;          // 0..7
    const int qid  = lane & 3;           // 0..3
    const int sub  = lane >> 3;          // 0..3
    const int rin  = lane & 7;           // 0..7

    const uint32_t* Qg = g_q + (size_t)bh * SS * DD;
    const uint32_t* Kg = g_k + (size_t)bh * SS * DD;
    const uint32_t* Vg = g_v + (size_t)bh * SS * DD;

    const int q0 = c * WIN_ + qb * 64;

    // ldmatrix fragment base offsets (bytes)
    const uint32_t qpFragOff = (uint32_t)((w * 16 + (sub & 1) * 8 + rin) * AST + (sub >> 1) * 4) * 4;  // A-frag (Q / P)
    const uint32_t kFragOff  = (uint32_t)(64 * AST + rin * AST + (sub & 1) * 4) * 4;                   // B-frag (K)

    {
        int r0 = tid >> 4;
        int dc = (tid & 15) * 4;
        #pragma unroll
        for (int p = 0; p < 8; p++) {
            int r = r0 + p * 8;
            *reinterpret_cast<uint4*>(&Qs[r * AST + dc]) =
                *reinterpret_cast<const uint4*>(&Qg[(size_t)(q0 + r) * DD + dc]);
        }
    }
    __syncthreads();

    uint32_t qf[8][4];
    #pragma unroll
    for (int ks = 0; ks < 8; ks++)
        ldsm_x4(qf[ks], smA + qpFragOff + (uint32_t)(ks * 8) * 4);

    float o[8][4];
    #pragma unroll
    for (int nf = 0; nf < 8; nf++)
        #pragma unroll
        for (int r = 0; r < 4; r++) o[nf][r] = 0.f;
    float m0 = -1e30f, m1 = -1e30f, l0 = 0.f, l1 = 0.f;

    const int qp0 = q0 + w * 16 + grp;
    const int qp1 = qp0 + 8;

    for (int kt = qb; kt <= qb + 8; kt++) {
        const int kbase = c * WIN_ - WIN_ + kt * 64;
        if (kbase >= SS || kbase < 0) continue;

        {
            int r0 = tid >> 4;
            int dc = (tid & 15) * 4;
            #pragma unroll
            for (int p = 0; p < 8; p++) {
                int r = r0 + p * 8;
                *reinterpret_cast<uint4*>(&Ks[r * AST + dc]) =
                    *reinterpret_cast<const uint4*>(&Kg[(size_t)(kbase + r) * DD + dc]);
                *reinterpret_cast<uint4*>(&Vs[r * AST + dc]) =
                    *reinterpret_cast<const uint4*>(&Vg[(size_t)(kbase + r) * DD + dc]);
            }
        }
        __syncthreads();

        float s[8][4];
        #pragma unroll
        for (int nf = 0; nf < 8; nf++)
            #pragma unroll
            for (int r = 0; r < 4; r++) s[nf][r] = 0.f;

        #pragma unroll
        for (int ks = 0; ks < 8; ks++) {
            #pragma unroll
            for (int nf = 0; nf < 8; nf++) {
                uint32_t b[2];
                ldsm_x2(b, smA + kFragOff + (uint32_t)(nf * 8 * AST + ks * 8) * 4);
                mma_tf32v(s[nf], qf[ks], b);
            }
        }

        float nm0 = m0, nm1 = m1;
        #pragma unroll
        for (int nf = 0; nf < 8; nf++) {
            int kp = kbase + nf * 8 + qid * 2;
            s[nf][0] = (kp     >= qp0 - WIN_ && kp     <= qp0 + WIN_) ? s[nf][0] : -1e30f;
            s[nf][1] = (kp + 1 >= qp0 - WIN_ && kp + 1 <= qp0 + WIN_) ? s[nf][1] : -1e30f;
            s[nf][2] = (kp     >= qp1 - WIN_ && kp     <= qp1 + WIN_) ? s[nf][2] : -1e30f;
            s[nf][3] = (kp + 1 >= qp1 - WIN_ && kp + 1 <= qp1 + WIN_) ? s[nf][3] : -1e30f;
            nm0 = fmaxf(nm0, fmaxf(s[nf][0], s[nf][1]));
            nm1 = fmaxf(nm1, fmaxf(s[nf][2], s[nf][3]));
        }
        nm0 = fmaxf(nm0, __shfl_xor_sync(0xffffffffu, nm0, 1));
        nm0 = fmaxf(nm0, __shfl_xor_sync(0xffffffffu, nm0, 2));
        nm1 = fmaxf(nm1, __shfl_xor_sync(0xffffffffu, nm1, 1));
        nm1 = fmaxf(nm1, __shfl_xor_sync(0xffffffffu, nm1, 2));

        float fac0 = __expf(m0 - nm0);
        float fac1 = __expf(m1 - nm1);
        m0 = nm0; m1 = nm1;

        float rs0 = 0.f, rs1 = 0.f;
        const int prow0 = (w * 16 + grp) * AST + qid * 2;
        const int prow1 = (w * 16 + grp + 8) * AST + qid * 2;
        #pragma unroll
        for (int nf = 0; nf < 8; nf++) {
            uint32_t u00 = f2tf(__expf(s[nf][0] - m0));
            uint32_t u01 = f2tf(__expf(s[nf][1] - m0));
            uint32_t u10 = f2tf(__expf(s[nf][2] - m1));
            uint32_t u11 = f2tf(__expf(s[nf][3] - m1));
            rs0 += __uint_as_float(u00) + __uint_as_float(u01);
            rs1 += __uint_as_float(u10) + __uint_as_float(u11);
            *reinterpret_cast<uint2*>(&Ps[prow0 + nf * 8]) = make_uint2(u00, u01);
            *reinterpret_cast<uint2*>(&Ps[prow1 + nf * 8]) = make_uint2(u10, u11);
        }
        rs0 += __shfl_xor_sync(0xffffffffu, rs0, 1);
        rs0 += __shfl_xor_sync(0xffffffffu, rs0, 2);
        rs1 += __shfl_xor_sync(0xffffffffu, rs1, 1);
        rs1 += __shfl_xor_sync(0xffffffffu, rs1, 2);
        l0 = l0 * fac0 + rs0;
        l1 = l1 * fac1 + rs1;

        #pragma unroll
        for (int nf = 0; nf < 8; nf++) {
            o[nf][0] *= fac0; o[nf][1] *= fac0;
            o[nf][2] *= fac1; o[nf][3] *= fac1;
        }
        __syncwarp();   // Ps rows warp-private; order stores before cross-lane ldmatrix reads

        #pragma unroll
        for (int ks = 0; ks < 8; ks++) {
            uint32_t a[4];
            ldsm_x4(a, smA + qpFragOff + (uint32_t)(ks * 8) * 4);
            #pragma unroll
            for (int nf = 0; nf < 8; nf++) {
                int vbase = (ks * 8 + qid) * AST + nf * 8 + grp;
                mma_tf32(o[nf], a, Vs[vbase], Vs[vbase + 4 * AST]);
            }
        }
        __syncthreads();
    }

    // epilogue: normalize + write ctx as tf32 bits
    const int b = bh >> 4, h = bh & 15;
    float inv0 = 1.f / l0, inv1 = 1.f / l1;
    const int row0 = q0 + w * 16 + grp;
    #pragma unroll
    for (int nf = 0; nf < 8; nf++) {
        int col = h * DD + nf * 8 + qid * 2;
        *reinterpret_cast<uint2*>(&g_ctx[((size_t)(b * SS + row0)) * EE + col]) =
            make_uint2(f2tf(o[nf][0] * inv0), f2tf(o[nf][1] * inv0));
        *reinterpret_cast<uint2*>(&g_ctx[((size_t)(b * SS + row0 + 8)) * EE + col]) =
            make_uint2(f2tf(o[nf][2] * inv1), f2tf(o[nf][3] * inv1));
    }
}

extern "C" void kernel_launch(void* const* d_in, const int* in_sizes, int n_in,
                              void* d_out, int out_size)
{
    (void)in_sizes; (void)n_in; (void)out_size;
    const float* x  = (const float*)d_in[0];
    const float* Wq = (const float*)d_in[1];
    const float* bq = (const float*)d_in[2];
    const float* Wk = (const float*)d_in[3];
    const float* bk = (const float*)d_in[4];
    const float* Wv = (const float*)d_in[5];
    const float* bv = (const float*)d_in[6];
    const float* Wo = (const float*)d_in[7];
    const float* bo = (const float*)d_in[8];
    float* out = (float*)d_out;

    cudaFuncSetAttribute(proj_mma<0>, cudaFuncAttributeMaxDynamicSharedMemorySize, SMEM_PROJ);
    cudaFuncSetAttribute(proj_mma<1>, cudaFuncAttributeMaxDynamicSharedMemorySize, SMEM_PROJ);
    cudaFuncSetAttribute(attn_mma_kernel, cudaFuncAttributeMaxDynamicSharedMemorySize, SMEM_ATTN);

    {
        size_t total4 = (XT_ELEMS + 4 * WT_ELEMS) / 4;
        int blocks = (int)((total4 + 255) / 256);
        conv_kernel<<<blocks, 256>>>(x, Wq, Wk, Wv, Wo);
    }

    dim3 gq(EE / 128, MM / 256, 3);
    proj_mma<0><<<gq, 256, SMEM_PROJ>>>(bq, bk, bv, nullptr);

    attn_mma_kernel<<<dim3(4, 16, BB * HH), 128, SMEM_ATTN>>>();

    dim3 go(EE / 128, MM / 256, 1);
    proj_mma<1><<<go, 256, SMEM_PROJ>>>(bo, nullptr, nullptr, out);
}

// round 12
// speedup vs baseline: 1.7342x; 1.7342x over previous
#include <cuda_runtime.h>
#include <cuda_fp16.h>
#include <math.h>
#include <stdint.h>

#define BB 2
#define SS 4096
#define EE 1024
#define HH 16
#define DD 64
#define WIN_ 256
#define MM (BB*SS)   // 8192

#define XT_ELEMS ((size_t)MM*EE)     // 8388608
#define WT_ELEMS ((size_t)EE*EE)     // 1048576

// scratch (allocation-free: __device__ globals); fp16 storage, fp32 accumulate
static __device__ __half g_xt[XT_ELEMS];             // x
static __device__ __half g_wt[4*WT_ELEMS];           // Wq,Wk,Wv,Wo
static __device__ __half g_q[(size_t)BB*HH*SS*DD];   // [b][h][s][d], rope'd + scaled
static __device__ __half g_k[(size_t)BB*HH*SS*DD];   // [b][h][s][d], rope'd
static __device__ __half g_v[(size_t)BB*HH*SS*DD];   // [b][h][s][d]
static __device__ __half g_ctx[(size_t)MM*EE];       // [b][s][e]

// rope over the HEAD axis: angle = head_idx * 10000^{-(j%32)/32}, interleaved rotation
__device__ __forceinline__ void rope_pair(float& v0, float& v1, int h, int j) {
    const float C = 0.28782313662425572f; // ln(10000)/32
    float invA = __expf(-(float)( j      & 31) * C);
    float invB = __expf(-(float)((j + 1) & 31) * C);
    float sa, ca, sb, cb;
    __sincosf((float)h * invA, &sa, &ca);
    __sincosf((float)h * invB, &sb, &cb);
    float r0 = v0 * ca - v1 * sa;
    float r1 = v1 * cb + v0 * sb;
    v0 = r0; v1 = r1;
}

// m16n8k16 fp16 MMA, fp32 accumulate
__device__ __forceinline__ void mma_f16(float (&c)[4], const uint32_t (&a)[4],
                                        const uint32_t b0, const uint32_t b1) {
    asm volatile(
        "mma.sync.aligned.m16n8k16.row.col.f32.f16.f16.f32 "
        "{%0,%1,%2,%3},{%4,%5,%6,%7},{%8,%9},{%0,%1,%2,%3};"
        : "+f"(c[0]), "+f"(c[1]), "+f"(c[2]), "+f"(c[3])
        : "r"(a[0]), "r"(a[1]), "r"(a[2]), "r"(a[3]), "r"(b0), "r"(b1));
}

__device__ __forceinline__ void ldsm_x4(uint32_t (&d)[4], uint32_t addr) {
    asm volatile("ldmatrix.sync.aligned.m8n8.x4.shared.b16 {%0,%1,%2,%3}, [%4];"
        : "=r"(d[0]), "=r"(d[1]), "=r"(d[2]), "=r"(d[3]) : "r"(addr));
}
__device__ __forceinline__ void ldsm_x2t(uint32_t (&d)[2], uint32_t addr) {
    asm volatile("ldmatrix.sync.aligned.m8n8.x2.trans.shared.b16 {%0,%1}, [%2];"
        : "=r"(d[0]), "=r"(d[1]) : "r"(addr));
}

__device__ __forceinline__ void cp16(uint32_t smem_addr, const void* gptr) {
    asm volatile("cp.async.cg.shared.global [%0], [%1], 16;" :: "r"(smem_addr), "l"(gptr));
}
#define CP_COMMIT() asm volatile("cp.async.commit_group;")
#define CP_WAIT2()  asm volatile("cp.async.wait_group 2;")

// ---------------- one-time fp16 conversion of x and W matrices ----------------
__global__ __launch_bounds__(256)
void conv_kernel(const float* __restrict__ x,
                 const float* __restrict__ wq, const float* __restrict__ wk,
                 const float* __restrict__ wv, const float* __restrict__ wo)
{
    size_t i8 = (size_t)blockIdx.x * 256 + threadIdx.x;   // 8-elem chunk
    const size_t x8 = XT_ELEMS / 8;
    const size_t w8 = WT_ELEMS / 8;
    if (i8 >= x8 + 4 * w8) return;
    const float* src; __half* dst; size_t off;
    if (i8 < x8) { src = x; dst = g_xt; off = i8 * 8; }
    else {
        size_t j = i8 - x8;
        int w = (int)(j / w8);
        off = (j - (size_t)w * w8) * 8;
        src = (w == 0) ? wq : (w == 1) ? wk : (w == 2) ? wv : wo;
        dst = g_wt + (size_t)w * WT_ELEMS;
    }
    float4 a = *reinterpret_cast<const float4*>(src + off);
    float4 b = *reinterpret_cast<const float4*>(src + off + 4);
    __half2 h[4];
    h[0] = __floats2half2_rn(a.x, a.y);
    h[1] = __floats2half2_rn(a.z, a.w);
    h[2] = __floats2half2_rn(b.x, b.y);
    h[3] = __floats2half2_rn(b.z, b.w);
    *reinterpret_cast<uint4*>(dst + off) = *reinterpret_cast<uint4*>(h);
}

// ---------------- projection GEMM (FP16 m16n8k16, cp.async 4-stage, 256x128 tile, 8 warps) ----------------
// MODE 0: A = g_xt, W = g_wt[z]; rope epilogue; writes g_q/g_k/g_v [b,h,s,d] fp16
// MODE 1: A = g_ctx, W = g_wt[3]; writes d_out [m,n] fp32
#define HSTR 72                                      // halves per smem row (64 + 8 pad)
#define STAGE_HALFS ((256 + 128) * HSTR)             // 27648
#define STAGE_BYTES (STAGE_HALFS * 2)                // 55296
#define NSTAGE 4
#define SMEM_PROJ (NSTAGE * STAGE_BYTES)             // 221184

template<int MODE>
__global__ __launch_bounds__(256, 1)
void proj_mma(const float* __restrict__ b0, const float* __restrict__ b1,
              const float* __restrict__ b2, float* __restrict__ out)
{
    extern __shared__ __half smh[];
    const uint32_t smem_b = (uint32_t)__cvta_generic_to_shared(smh);

    const int z = blockIdx.z;
    const __half* A = (MODE == 1) ? g_ctx : g_xt;
    const __half* W = g_wt + (size_t)((MODE == 1) ? 3 : z) * WT_ELEMS;
    const float* bias = (MODE == 1) ? b0 : (z == 0 ? b0 : (z == 1 ? b1 : b2));

    const int tid   = threadIdx.x;
    const int lane  = tid & 31;
    const int warp  = tid >> 5;            // 0..7
    const int warpM = warp >> 1;           // 0..3 -> 64-row slab
    const int warpN = warp & 1;            // 0..1 -> 64-col slab
    const int grp   = lane >> 2;           // 0..7
    const int qid   = lane & 3;            // 0..3
    const int sub   = lane >> 3;           // 0..3
    const int rin   = lane & 7;            // 0..7
    const int mBase = blockIdx.y * 256;
    const int nBase = blockIdx.x * 128;

    // ldmatrix per-lane byte offsets
    const uint32_t aFragOff = (uint32_t)(((warpM * 64 + (sub & 1) * 8 + rin) * HSTR + (sub >> 1) * 8) * 2);
    const uint32_t bFragOff = (uint32_t)((256 * HSTR + (warpN * 64 + (sub & 1) * 8 + rin) * HSTR + (sub >> 1) * 8) * 2);

    // async stage loader: A 256x64h, B 128x64h (16B chunks)
    auto issue = [&](int stg, int k0) {
        uint32_t base = smem_b + stg * STAGE_BYTES;
        int kofs = k0 * 64;
        #pragma unroll
        for (int p = 0; p < 8; p++) {
            int ch = tid + p * 256;            // 0..2047
            int row = ch >> 3, c8 = (ch & 7) * 8;
            cp16(base + (uint32_t)((row * HSTR + c8) * 2),
                 A + (size_t)(mBase + row) * EE + kofs + c8);
        }
        #pragma unroll
        for (int p = 0; p < 4; p++) {
            int ch = tid + p * 256;            // 0..1023
            int row = ch >> 3, c8 = (ch & 7) * 8;
            cp16(base + (uint32_t)((256 * HSTR + row * HSTR + c8) * 2),
                 W + (size_t)(nBase + row) * EE + kofs + c8);
        }
    };

    float acc[4][8][4];
    #pragma unroll
    for (int mf = 0; mf < 4; mf++)
        #pragma unroll
        for (int nf = 0; nf < 8; nf++)
            #pragma unroll
            for (int r = 0; r < 4; r++) acc[mf][nf][r] = 0.f;

    const int NIT = EE / 64;   // 16
    issue(0, 0); CP_COMMIT();
    issue(1, 1); CP_COMMIT();
    issue(2, 2); CP_COMMIT();

    int stage = 0;
    for (int k0 = 0; k0 < NIT; k0++) {
        CP_WAIT2();
        __syncthreads();
        if (k0 + 3 < NIT) {
            int ns = stage + 3; if (ns >= NSTAGE) ns -= NSTAGE;
            issue(ns, k0 + 3);
        }
        CP_COMMIT();

        const uint32_t aBase = smem_b + stage * STAGE_BYTES + aFragOff;
        const uint32_t bBase = smem_b + stage * STAGE_BYTES + bFragOff;

        #pragma unroll
        for (int ks = 0; ks < 4; ks++) {
            uint32_t af[4][4];
            #pragma unroll
            for (int mf = 0; mf < 4; mf++)
                ldsm_x4(af[mf], aBase + (uint32_t)((mf * 16 * HSTR + ks * 16) * 2));
            uint32_t bf[4][4];
            #pragma unroll
            for (int pr = 0; pr < 4; pr++)
                ldsm_x4(bf[pr], bBase + (uint32_t)((pr * 16 * HSTR + ks * 16) * 2));
            #pragma unroll
            for (int mf = 0; mf < 4; mf++)
                #pragma unroll
                for (int pr = 0; pr < 4; pr++) {
                    mma_f16(acc[mf][pr * 2 + 0], af[mf], bf[pr][0], bf[pr][2]);
                    mma_f16(acc[mf][pr * 2 + 1], af[mf], bf[pr][1], bf[pr][3]);
                }
        }

        stage++; if (stage >= NSTAGE) stage = 0;
    }

    // epilogue: bias (+rope/scale for MODE 0), scatter
    #pragma unroll
    for (int mf = 0; mf < 4; mf++) {
        #pragma unroll
        for (int half_ = 0; half_ < 2; half_++) {
            int row = mBase + warpM * 64 + mf * 16 + grp + half_ * 8;
            int bb   = row >> 12;
            int srow = row & 4095;
            #pragma unroll
            for (int nf = 0; nf < 8; nf++) {
                int col = nBase + warpN * 64 + nf * 8 + qid * 2;
                float v0 = acc[mf][nf][half_ * 2 + 0] + bias[col];
                float v1 = acc[mf][nf][half_ * 2 + 1] + bias[col + 1];
                if (MODE == 1) {
                    *reinterpret_cast<float2*>(&out[(size_t)row * EE + col]) = make_float2(v0, v1);
                } else {
                    int h = col >> 6;
                    int j = col & 63;     // even
                    if (z <= 1) rope_pair(v0, v1, h, j);
                    if (z == 0) { v0 *= 0.125f; v1 *= 0.125f; }
                    __half* dst = (z == 0) ? g_q : (z == 1) ? g_k : g_v;
                    size_t idx = (((size_t)bb * HH + h) * SS + srow) * DD + j;
                    *reinterpret_cast<__half2*>(&dst[idx]) = __floats2half2_rn(v0, v1);
                }
            }
        }
    }
}

// ---------------- sliding-window attention (flash-style, FP16 m16n8k16) ----------------
// grid (qb=4, c=16, bh=32); block 128 (4 warps); each warp owns 16 query rows.
#define AST_H 72                                   // smem stride (halves)
#define SMEM_ATTN (3 * 64 * AST_H * 2)             // Qs(->Ps) + Ks + Vs = 27648 B

__global__ __launch_bounds__(128)
void attn_mma_kernel()
{
    extern __shared__ __half smh[];
    __half* Qs = smh;                   // 64 x AST_H (reused as Ps after Q frags in regs)
    __half* Ks = smh + 64 * AST_H;
    __half* Vs = smh + 2 * 64 * AST_H;
    __half* Ps = Qs;
    const uint32_t smA = (uint32_t)__cvta_generic_to_shared(smh);

    const int qb = blockIdx.x;
    const int c  = blockIdx.y;
    const int bh = blockIdx.z;
    const int tid  = threadIdx.x;
    const int w    = tid >> 5;
    const int lane = tid & 31;
    const int grp  = lane >> 2;
    const int qid  = lane & 3;
    const int sub  = lane >> 3;
    const int rin  = lane & 7;

    const __half* Qg = g_q + (size_t)bh * SS * DD;
    const __half* Kg = g_k + (size_t)bh * SS * DD;
    const __half* Vg = g_v + (size_t)bh * SS * DD;

    const int q0 = c * WIN_ + qb * 64;

    // ldmatrix per-lane byte offsets
    const uint32_t qpFragOff = (uint32_t)(((w * 16 + (sub & 1) * 8 + rin) * AST_H + (sub >> 1) * 8) * 2);  // A-frag (Q / P)
    const uint32_t kFragOff  = (uint32_t)((64 * AST_H + ((sub & 1) * 8 + rin) * AST_H + (sub >> 1) * 8) * 2); // B-frag (K)
    const uint32_t vFragOff  = (uint32_t)((2 * 64 * AST_H + ((sub & 1) * 8 + rin) * AST_H) * 2);              // B-frag (V, .trans)

    {   // Q tile: 64 rows x 64 halves (8 x 16B chunks per row)
        #pragma unroll
        for (int p = 0; p < 4; p++) {
            int ch = tid + p * 128;            // 0..511
            int r = ch >> 3, c8 = (ch & 7) * 8;
            *reinterpret_cast<uint4*>(&Qs[r * AST_H + c8]) =
                *reinterpret_cast<const uint4*>(&Qg[(size_t)(q0 + r) * DD + c8]);
        }
    }
    __syncthreads();

    uint32_t qf[4][4];
    #pragma unroll
    for (int ks = 0; ks < 4; ks++)
        ldsm_x4(qf[ks], smA + qpFragOff + (uint32_t)(ks * 16 * 2));

    float o[8][4];
    #pragma unroll
    for (int nf = 0; nf < 8; nf++)
        #pragma unroll
        for (int r = 0; r < 4; r++) o[nf][r] = 0.f;
    float m0 = -1e30f, m1 = -1e30f, l0 = 0.f, l1 = 0.f;

    const int qp0 = q0 + w * 16 + grp;
    const int qp1 = qp0 + 8;

    for (int kt = qb; kt <= qb + 8; kt++) {
        const int kbase = c * WIN_ - WIN_ + kt * 64;
        if (kbase >= SS || kbase < 0) continue;

        {   // K/V tiles
            #pragma unroll
            for (int p = 0; p < 4; p++) {
                int ch = tid + p * 128;
                int r = ch >> 3, c8 = (ch & 7) * 8;
                *reinterpret_cast<uint4*>(&Ks[r * AST_H + c8]) =
                    *reinterpret_cast<const uint4*>(&Kg[(size_t)(kbase + r) * DD + c8]);
                *reinterpret_cast<uint4*>(&Vs[r * AST_H + c8]) =
                    *reinterpret_cast<const uint4*>(&Vg[(size_t)(kbase + r) * DD + c8]);
            }
        }
        __syncthreads();

        float s[8][4];
        #pragma unroll
        for (int nf = 0; nf < 8; nf++)
            #pragma unroll
            for (int r = 0; r < 4; r++) s[nf][r] = 0.f;

        #pragma unroll
        for (int ks = 0; ks < 4; ks++) {
            #pragma unroll
            for (int pr = 0; pr < 4; pr++) {
                uint32_t bk[4];
                ldsm_x4(bk, smA + kFragOff + (uint32_t)((pr * 16 * AST_H + ks * 16) * 2));
                mma_f16(s[pr * 2 + 0], qf[ks], bk[0], bk[2]);
                mma_f16(s[pr * 2 + 1], qf[ks], bk[1], bk[3]);
            }
        }

        float nm0 = m0, nm1 = m1;
        #pragma unroll
        for (int nf = 0; nf < 8; nf++) {
            int kp = kbase + nf * 8 + qid * 2;
            s[nf][0] = (kp     >= qp0 - WIN_ && kp     <= qp0 + WIN_) ? s[nf][0] : -1e30f;
            s[nf][1] = (kp + 1 >= qp0 - WIN_ && kp + 1 <= qp0 + WIN_) ? s[nf][1] : -1e30f;
            s[nf][2] = (kp     >= qp1 - WIN_ && kp     <= qp1 + WIN_) ? s[nf][2] : -1e30f;
            s[nf][3] = (kp + 1 >= qp1 - WIN_ && kp + 1 <= qp1 + WIN_) ? s[nf][3] : -1e30f;
            nm0 = fmaxf(nm0, fmaxf(s[nf][0], s[nf][1]));
            nm1 = fmaxf(nm1, fmaxf(s[nf][2], s[nf][3]));
        }
        nm0 = fmaxf(nm0, __shfl_xor_sync(0xffffffffu, nm0, 1));
        nm0 = fmaxf(nm0, __shfl_xor_sync(0xffffffffu, nm0, 2));
        nm1 = fmaxf(nm1, __shfl_xor_sync(0xffffffffu, nm1, 1));
        nm1 = fmaxf(nm1, __shfl_xor_sync(0xffffffffu, nm1, 2));

        float fac0 = __expf(m0 - nm0);
        float fac1 = __expf(m1 - nm1);
        m0 = nm0; m1 = nm1;

        float rs0 = 0.f, rs1 = 0.f;
        const int prow0 = (w * 16 + grp) * AST_H + qid * 2;
        const int prow1 = (w * 16 + grp + 8) * AST_H + qid * 2;
        #pragma unroll
        for (int nf = 0; nf < 8; nf++) {
            // round P to fp16 BEFORE summing so l matches what the MMA multiplies
            __half h00 = __float2half_rn(__expf(s[nf][0] - m0));
            __half h01 = __float2half_rn(__expf(s[nf][1] - m0));
            __half h10 = __float2half_rn(__expf(s[nf][2] - m1));
            __half h11 = __float2half_rn(__expf(s[nf][3] - m1));
            rs0 += __half2float(h00) + __half2float(h01);
            rs1 += __half2float(h10) + __half2float(h11);
            *reinterpret_cast<__half2*>(&Ps[prow0 + nf * 8]) = __halves2half2(h00, h01);
            *reinterpret_cast<__half2*>(&Ps[prow1 + nf * 8]) = __halves2half2(h10, h11);
        }
        rs0 += __shfl_xor_sync(0xffffffffu, rs0, 1);
        rs0 += __shfl_xor_sync(0xffffffffu, rs0, 2);
        rs1 += __shfl_xor_sync(0xffffffffu, rs1, 1);
        rs1 += __shfl_xor_sync(0xffffffffu, rs1, 2);
        l0 = l0 * fac0 + rs0;
        l1 = l1 * fac1 + rs1;

        #pragma unroll
        for (int nf = 0; nf < 8; nf++) {
            o[nf][0] *= fac0; o[nf][1] *= fac0;
            o[nf][2] *= fac1; o[nf][3] *= fac1;
        }
        __syncwarp();   // Ps rows warp-private; order stores before cross-lane ldmatrix reads

        // O += P @ V  (V consumed k-major via ldmatrix.trans)
        #pragma unroll
        for (int ks = 0; ks < 4; ks++) {
            uint32_t a[4];
            ldsm_x4(a, smA + qpFragOff + (uint32_t)(ks * 16 * 2));
            #pragma unroll
            for (int nf = 0; nf < 8; nf++) {
                uint32_t bv[2];
                ldsm_x2t(bv, smA + vFragOff + (uint32_t)((ks * 16 * AST_H + nf * 8) * 2));
                mma_f16(o[nf], a, bv[0], bv[1]);
            }
        }
        __syncthreads();
    }

    // epilogue: normalize + write ctx as fp16
    const int b = bh >> 4, h = bh & 15;
    float inv0 = 1.f / l0, inv1 = 1.f / l1;
    const int row0 = q0 + w * 16 + grp;
    #pragma unroll
    for (int nf = 0; nf < 8; nf++) {
        int col = h * DD + nf * 8 + qid * 2;
        *reinterpret_cast<__half2*>(&g_ctx[((size_t)(b * SS + row0)) * EE + col]) =
            __floats2half2_rn(o[nf][0] * inv0, o[nf][1] * inv0);
        *reinterpret_cast<__half2*>(&g_ctx[((size_t)(b * SS + row0 + 8)) * EE + col]) =
            __floats2half2_rn(o[nf][2] * inv1, o[nf][3] * inv1);
    }
}

extern "C" void kernel_launch(void* const* d_in, const int* in_sizes, int n_in,
                              void* d_out, int out_size)
{
    (void)in_sizes; (void)n_in; (void)out_size;
    const float* x  = (const float*)d_in[0];
    const float* Wq = (const float*)d_in[1];
    const float* bq = (const float*)d_in[2];
    const float* Wk = (const float*)d_in[3];
    const float* bk = (const float*)d_in[4];
    const float* Wv = (const float*)d_in[5];
    const float* bv = (const float*)d_in[6];
    const float* Wo = (const float*)d_in[7];
    const float* bo = (const float*)d_in[8];
    float* out = (float*)d_out;

    cudaFuncSetAttribute(proj_mma<0>, cudaFuncAttributeMaxDynamicSharedMemorySize, SMEM_PROJ);
    cudaFuncSetAttribute(proj_mma<1>, cudaFuncAttributeMaxDynamicSharedMemorySize, SMEM_PROJ);
    cudaFuncSetAttribute(attn_mma_kernel, cudaFuncAttributeMaxDynamicSharedMemorySize, SMEM_ATTN);

    {
        size_t total8 = (XT_ELEMS + 4 * WT_ELEMS) / 8;
        int blocks = (int)((total8 + 255) / 256);
        conv_kernel<<<blocks, 256>>>(x, Wq, Wk, Wv, Wo);
    }

    dim3 gq(EE / 128, MM / 256, 3);
    proj_mma<0><<<gq, 256, SMEM_PROJ>>>(bq, bk, bv, nullptr);

    attn_mma_kernel<<<dim3(4, 16, BB * HH), 128, SMEM_ATTN>>>();

    dim3 go(EE / 128, MM / 256, 1);
    proj_mma<1><<<go, 256, SMEM_PROJ>>>(bo, nullptr, nullptr, out);
}